// round 6
// baseline (speedup 1.0000x reference)
#include <cuda_runtime.h>
#include <math.h>

// ---------------- problem constants ----------------
#define Nn      129
#define Fdim    262144
#define Ee      16384
#define GRID    148
#define NTHR    1024
#define NCOPY   8
#define PADS    64                      // 256B stride between accumulator slots
#define XPAD    32                      // 128B stride for xw accumulators
#define NSLOT   (3 * Nn)                // 387 (ch,node) slots
#define SEGF4   256                     // float4 per segment (4KB)
#define SEGROW  256                     // segments per row = (Fdim/4)/SEGF4
#define TILETOT (Nn * SEGROW)           // 33024 warp tiles
#define DOTB    144                     // blocks doing the dot
#define DEGB    4                       // blocks doing deg scatter (144..147)
#define PART2   16                      // blocks participating after barrier 0

// ---------------- device scratch ----------------
__device__ float    g_xwa[Nn * XPAD];
__device__ float    g_deg[NSLOT * PADS];
__device__ float    g_h1 [NCOPY * NSLOT * PADS];
__device__ float    g_h2 [NCOPY * NSLOT * PADS];
__device__ unsigned g_bar[4];

// ---------------- grid barrier: monotonic, replay-safe, atomic polling ----------------
__device__ __forceinline__ void gridbar(int k, unsigned cnt) {
    __syncthreads();
    __threadfence();
    if (threadIdx.x == 0) {
        unsigned v = atomicAdd(&g_bar[k], 1u);
        unsigned target = (v / cnt) * cnt + cnt;
        while (atomicAdd(&g_bar[k], 0u) < target) __nanosleep(32);
    }
    __syncthreads();
    __threadfence();
}

__device__ __forceinline__ float eluf(float a) { return a > 0.f ? a : expm1f(a); }

__global__ void __launch_bounds__(NTHR, 1)
dgcnn_fused(const float* __restrict__ x,   const float* __restrict__ w,
            const int*   __restrict__ ei,  const float* __restrict__ ea,
            const float* __restrict__ g1b, const float* __restrict__ g2W,
            const float* __restrict__ g2b,
            const float* __restrict__ c1w, const float* __restrict__ c1b,
            const float* __restrict__ c2w, const float* __restrict__ c2b,
            const float* __restrict__ f1W, const float* __restrict__ f1b,
            const float* __restrict__ f2W, const float* __restrict__ f2b,
            const float* __restrict__ f3W, const float* __restrict__ f3b,
            float* __restrict__ out) {
    __shared__ float s_xw[Nn], s_dinv[NSLOT], s_h1f[NSLOT], s_h2a[NSLOT];
    __shared__ float z0[NSLOT], z1[NSLOT];
    __shared__ float c1s[3 * 3 * 127], p1s[3 * 3 * 125], c2s[3 * 123];
    __shared__ float allx[363], f1s[32], f2s[6];

    const int t    = threadIdx.x;
    const int bid  = blockIdx.x;
    const int lane = t & 31, warp = t >> 5;

    // ================= PHASE 1: warp-autonomous dot + deg scatter =================
    if (bid < DOTB) {
        // warp tile = 256 float4 (4KB) of one row; 4x+4w float4 in flight per batch
        for (int tile = bid * 32 + warp; tile < TILETOT; tile += DOTB * 32) {
            const int row = tile >> 8, seg = tile & 255;
            const float4* __restrict__ xp =
                (const float4*)x + (size_t)row * (Fdim / 4) + seg * SEGF4 + lane;
            const float4* __restrict__ wp =
                (const float4*)w + seg * SEGF4 + lane;
            float4 acc = make_float4(0.f, 0.f, 0.f, 0.f);
            {
                float4 a0 = __ldcv(xp);
                float4 a1 = __ldcv(xp + 32);
                float4 a2 = __ldcv(xp + 64);
                float4 a3 = __ldcv(xp + 96);
                float4 b0 = __ldg(wp);
                float4 b1 = __ldg(wp + 32);
                float4 b2 = __ldg(wp + 64);
                float4 b3 = __ldg(wp + 96);
                acc.x = fmaf(a0.x, b0.x, acc.x); acc.y = fmaf(a0.y, b0.y, acc.y);
                acc.z = fmaf(a0.z, b0.z, acc.z); acc.w = fmaf(a0.w, b0.w, acc.w);
                acc.x = fmaf(a1.x, b1.x, acc.x); acc.y = fmaf(a1.y, b1.y, acc.y);
                acc.z = fmaf(a1.z, b1.z, acc.z); acc.w = fmaf(a1.w, b1.w, acc.w);
                acc.x = fmaf(a2.x, b2.x, acc.x); acc.y = fmaf(a2.y, b2.y, acc.y);
                acc.z = fmaf(a2.z, b2.z, acc.z); acc.w = fmaf(a2.w, b2.w, acc.w);
                acc.x = fmaf(a3.x, b3.x, acc.x); acc.y = fmaf(a3.y, b3.y, acc.y);
                acc.z = fmaf(a3.z, b3.z, acc.z); acc.w = fmaf(a3.w, b3.w, acc.w);
            }
            {
                float4 a0 = __ldcv(xp + 128);
                float4 a1 = __ldcv(xp + 160);
                float4 a2 = __ldcv(xp + 192);
                float4 a3 = __ldcv(xp + 224);
                float4 b0 = __ldg(wp + 128);
                float4 b1 = __ldg(wp + 160);
                float4 b2 = __ldg(wp + 192);
                float4 b3 = __ldg(wp + 224);
                acc.x = fmaf(a0.x, b0.x, acc.x); acc.y = fmaf(a0.y, b0.y, acc.y);
                acc.z = fmaf(a0.z, b0.z, acc.z); acc.w = fmaf(a0.w, b0.w, acc.w);
                acc.x = fmaf(a1.x, b1.x, acc.x); acc.y = fmaf(a1.y, b1.y, acc.y);
                acc.z = fmaf(a1.z, b1.z, acc.z); acc.w = fmaf(a1.w, b1.w, acc.w);
                acc.x = fmaf(a2.x, b2.x, acc.x); acc.y = fmaf(a2.y, b2.y, acc.y);
                acc.z = fmaf(a2.z, b2.z, acc.z); acc.w = fmaf(a2.w, b2.w, acc.w);
                acc.x = fmaf(a3.x, b3.x, acc.x); acc.y = fmaf(a3.y, b3.y, acc.y);
                acc.z = fmaf(a3.z, b3.z, acc.z); acc.w = fmaf(a3.w, b3.w, acc.w);
            }
            float s = (acc.x + acc.y) + (acc.z + acc.w);
#pragma unroll
            for (int o = 16; o > 0; o >>= 1) s += __shfl_down_sync(0xffffffffu, s, o);
            if (lane == 0) atomicAdd(&g_xwa[row * XPAD], s);
        }
    } else {
        // blocks 144..147: degree scatter (hidden under the dot)
        for (int e = (bid - DOTB) * NTHR + t; e < Ee; e += DEGB * NTHR) {
            int cc = ei[Ee + e];
#pragma unroll
            for (int ch = 0; ch < 3; ch++)
                atomicAdd(&g_deg[(ch * Nn + cc) * PADS], ea[e * 3 + ch]);
        }
    }

    gridbar(0, GRID);
    if (bid >= PART2) return;                          // only blocks 0..15 continue

    // ================= PHASE 2: dinv/xw -> smem, edge agg layer 1 =================
    if (t < Nn) s_xw[t] = __ldcg(&g_xwa[t * XPAD]);
    if (t < NSLOT) {
        float d = __ldcg(&g_deg[t * PADS]) + 1.0f;     // +1 self loop
        s_dinv[t] = (d > 0.f) ? rsqrtf(d) : 0.f;
    }
    __syncthreads();

    {
        int e = bid * NTHR + t;                        // exactly covers 16384 edges
        int r = ei[e], c = ei[Ee + e];
        int cp = (bid & (NCOPY - 1)) * NSLOT;
#pragma unroll
        for (int ch = 0; ch < 3; ch++) {
            float ew  = ea[e * 3 + ch];
            float nrm = s_dinv[ch * Nn + r] * ew * s_dinv[ch * Nn + c];
            atomicAdd(&g_h1[(cp + ch * Nn + c) * PADS], nrm * s_xw[r]);
        }
    }

    gridbar(1, PART2);

    // ================= PHASE 3: finalize h1, edge agg layer 2 =================
    const float b1 = g1b[0], W2 = g2W[0];
    if (t < NSLOT) {
        float acc1 = 0.f;
#pragma unroll
        for (int c = 0; c < NCOPY; c++) acc1 += __ldcg(&g_h1[(c * NSLOT + t) * PADS]);
        float di = s_dinv[t];
        s_h1f[t] = acc1 + di * di * s_xw[t % Nn] + b1;
    }
    __syncthreads();

    {
        int e = bid * NTHR + t;
        int r = ei[e], c = ei[Ee + e];
        int cp = (bid & (NCOPY - 1)) * NSLOT;
#pragma unroll
        for (int ch = 0; ch < 3; ch++) {
            float ew  = ea[e * 3 + ch];
            float nrm = s_dinv[ch * Nn + r] * ew * s_dinv[ch * Nn + c];
            atomicAdd(&g_h2[(cp + ch * Nn + c) * PADS], nrm * s_h1f[ch * Nn + r] * W2);
        }
    }
    // dead scratch zeroing for next replay
    if (bid == 9 && t < NSLOT) g_deg[t * PADS] = 0.f;
    if (bid == 10 && t < Nn)   g_xwa[t * XPAD] = 0.f;

    gridbar(2, PART2);

    // ================= PHASE 4: cleanup + tail =================
    if (bid != 0) {
        if (bid <= NCOPY) {                            // blocks 1..8 zero h1 copies
            int c = bid - 1;
            if (t < NSLOT) g_h1[(c * NSLOT + t) * PADS] = 0.f;
        }
        return;
    }

    // ---- block 0: finalize h2, zero its copies ----
    const float b2 = g2b[0];
    if (t < NSLOT) {
        float acc2 = 0.f;
#pragma unroll
        for (int c = 0; c < NCOPY; c++) {
            acc2 += __ldcg(&g_h2[(c * NSLOT + t) * PADS]);
            g_h2[(c * NSLOT + t) * PADS] = 0.f;
        }
        float di = s_dinv[t];
        s_h2a[t] = acc2 + di * di * s_h1f[t] * W2 + b2;
    }
    __syncthreads();

    // ---- SortPool (3 channels parallel): stable descending by h2 ----
    if (t < NSLOT) {
        int ch = t / Nn, tt = t - ch * Nn;
        float key = s_h2a[ch * Nn + tt];
        float v1  = s_h1f[ch * Nn + tt];
        int rank = 0;
        for (int m = 0; m < Nn; m++) {
            float km = s_h2a[ch * Nn + m];
            rank += (km > key) || (km == key && m < tt);
        }
        z0[ch * Nn + rank] = v1;
        z1[ch * Nn + rank] = key;
    }
    __syncthreads();

    // ---- conv1: 2->3 ch, k=3 -> 127 (x3 graph channels) ----
    if (t < 3 * 127) {
        int ch = t / 127, tt = t - ch * 127;
#pragma unroll
        for (int o = 0; o < 3; o++) {
            float a = c1b[o];
#pragma unroll
            for (int k = 0; k < 3; k++) {
                a = fmaf(c1w[o * 6 + k],     z0[ch * Nn + tt + k], a);
                a = fmaf(c1w[o * 6 + 3 + k], z1[ch * Nn + tt + k], a);
            }
            c1s[(ch * 3 + o) * 127 + tt] = a;
        }
    }
    __syncthreads();

    // ---- maxpool3 -> 125 ----
    if (t < 3 * 125) {
        int ch = t / 125, tt = t - ch * 125;
#pragma unroll
        for (int o = 0; o < 3; o++) {
            const float* p = &c1s[(ch * 3 + o) * 127 + tt];
            p1s[(ch * 3 + o) * 125 + tt] = fmaxf(p[0], fmaxf(p[1], p[2]));
        }
    }
    __syncthreads();

    // ---- conv2: 3->1, k=3 -> 123 ----
    if (t < 3 * 123) {
        int ch = t / 123, tt = t - ch * 123;
        float a = c2b[0];
#pragma unroll
        for (int in = 0; in < 3; in++)
#pragma unroll
            for (int k = 0; k < 3; k++)
                a = fmaf(c2w[in * 3 + k], p1s[(ch * 3 + in) * 125 + tt + k], a);
        c2s[ch * 123 + tt] = a;
    }
    __syncthreads();

    // ---- maxpool3 -> 121 ----
    if (t < 3 * 121) {
        int ch = t / 121, tt = t - ch * 121;
        const float* p = &c2s[ch * 123 + tt];
        allx[ch * 121 + tt] = fmaxf(p[0], fmaxf(p[1], p[2]));
    }
    __syncthreads();

    // ---- fc1: 363->32, elu — warp per output ----
    {
        float a = 0.f;
        for (int i = lane; i < 363; i += 32) a = fmaf(allx[i], f1W[i * 32 + warp], a);
#pragma unroll
        for (int s = 16; s > 0; s >>= 1) a += __shfl_down_sync(0xffffffffu, a, s);
        if (lane == 0) f1s[warp] = eluf(a + f1b[warp]);
    }
    __syncthreads();
    // ---- fc2: 32->6, elu ----
    if (t < 6) {
        float a = f2b[t];
#pragma unroll
        for (int i = 0; i < 32; i++) a = fmaf(f1s[i], f2W[i * 6 + t], a);
        f2s[t] = eluf(a);
    }
    __syncthreads();
    // ---- fc3: 6->2 ----
    if (t < 2) {
        float a = f3b[t];
#pragma unroll
        for (int i = 0; i < 6; i++) a = fmaf(f2s[i], f3W[i * 2 + t], a);
        out[t] = a;
    }
}

// ---------------- launch ----------------
extern "C" void kernel_launch(void* const* d_in, const int* in_sizes, int n_in,
                              void* d_out, int out_size) {
    const float* x    = (const float*)d_in[0];
    const int*   ei   = (const int*)  d_in[1];
    const float* ea   = (const float*)d_in[2];
    const float* g1W  = (const float*)d_in[3];
    const float* g1b  = (const float*)d_in[4];
    const float* g2W  = (const float*)d_in[5];
    const float* g2b  = (const float*)d_in[6];
    const float* c1w  = (const float*)d_in[7];
    const float* c1b  = (const float*)d_in[8];
    const float* c2w  = (const float*)d_in[9];
    const float* c2b  = (const float*)d_in[10];
    const float* f1W  = (const float*)d_in[11];
    const float* f1b  = (const float*)d_in[12];
    const float* f2W  = (const float*)d_in[13];
    const float* f2b  = (const float*)d_in[14];
    const float* f3W  = (const float*)d_in[15];
    const float* f3b  = (const float*)d_in[16];
    float* out = (float*)d_out;

    dgcnn_fused<<<GRID, NTHR>>>(x, g1W, ei, ea, g1b, g2W, g2b,
                                c1w, c1b, c2w, c2b,
                                f1W, f1b, f2W, f2b, f3W, f3b, out);
}